// round 9
// baseline (speedup 1.0000x reference)
#include <cuda_runtime.h>

#define PH 7
#define PW 7
#define ROI_SCALE 0.0625f

#define N_IMG 4
#define C_DIM 128
#define H_DIM 50
#define W_DIM 50
#define HW (H_DIM * W_DIM)

// Bit-exact vs the as-executed JAX reference: x/7 computed as x * fl(1/7),
// fl(1/7) = 0x3E124925 (rounds up). DO NOT change.
#define RECIP7_BITS 0x3E124925u

// NHWC scratch: [b][h][w][c]  (5.12 MB static device array — no allocation)
__device__ float g_featT[N_IMG * HW * C_DIM];

// ---------------- NCHW -> NHWC transpose (per-b 128 x 2500 matrix T) -------
__global__ void transpose_kernel(const float* __restrict__ feat) {
    __shared__ float tile[32][33];
    int b   = blockIdx.z;
    int hw0 = blockIdx.x * 32;   // position dim (fast in source)
    int c0  = blockIdx.y * 32;   // channel dim

    const float* src = feat + (size_t)b * C_DIM * HW;
    float* dst = g_featT + (size_t)b * HW * C_DIM;

    int tx = threadIdx.x;        // 0..31
    int ty = threadIdx.y;        // 0..7

#pragma unroll
    for (int j = 0; j < 32; j += 8) {
        int c  = c0 + ty + j;
        int hw = hw0 + tx;
        if (hw < HW)
            tile[ty + j][tx] = src[c * HW + hw];
    }
    __syncthreads();
#pragma unroll
    for (int j = 0; j < 32; j += 8) {
        int hw = hw0 + ty + j;
        int c  = c0 + tx;
        if (hw < HW)
            dst[hw * C_DIM + c] = tile[tx][ty + j];
    }
}

// ---------------- main pooling: one block = one (k, ph); thread = channel ---
__global__ void __launch_bounds__(C_DIM) roi_pool_kernel(
        const float* __restrict__ rois,
        float* __restrict__ out) {
    int k  = blockIdx.x;
    int ph = blockIdx.y;
    int c  = threadIdx.x;

    // Uniform per-block decode (every thread computes the same values;
    // branches below stay warp-uniform).
    const float* r = rois + k * 5;
    int b  = (int)r[0];
    int x1 = (int)rintf(__fmul_rn(r[1], ROI_SCALE));
    int y1 = (int)rintf(__fmul_rn(r[2], ROI_SCALE));
    int x2 = (int)rintf(__fmul_rn(r[3], ROI_SCALE));
    int y2 = (int)rintf(__fmul_rn(r[4], ROI_SCALE));

    float roi_w = (float)max(x2 - x1 + 1, 1);
    float roi_h = (float)max(y2 - y1 + 1, 1);
    const float recip7 = __uint_as_float(RECIP7_BITS);
    float bin_w = __fmul_rn(roi_w, recip7);
    float bin_h = __fmul_rn(roi_h, recip7);

    float phf = (float)ph;
    int hstart = min(max((int)floorf(__fmul_rn(phf, bin_h)) + y1, 0), H_DIM);
    int hend   = min(max((int)ceilf(__fmul_rn(phf + 1.0f, bin_h)) + y1, 0), H_DIM);

    int ws[PW], we[PW];
#pragma unroll
    for (int j = 0; j < PW; ++j) {
        float jf = (float)j;
        ws[j] = min(max((int)floorf(__fmul_rn(jf, bin_w)) + x1, 0), W_DIM);
        we[j] = min(max((int)ceilf(__fmul_rn(jf + 1.0f, bin_w)) + x1, 0), W_DIM);
    }

    const float* baseb = g_featT + (size_t)b * HW * C_DIM + c;

    float acc[PW];
#pragma unroll
    for (int j = 0; j < PW; ++j) acc[j] = -1e30f;

    for (int h = hstart; h < hend; ++h) {
        const float* rowp = baseb + h * (W_DIM * C_DIM);
#pragma unroll
        for (int j = 0; j < PW; ++j) {
            float m = acc[j];
            for (int w = ws[j]; w < we[j]; ++w) {
                m = fmaxf(m, rowp[w * C_DIM]);   // 128B coalesced per warp
            }
            acc[j] = m;
        }
    }

    bool hempty = (hend <= hstart);
    float* op = out + (((size_t)k * C_DIM + c) * PH + ph) * PW;
#pragma unroll
    for (int j = 0; j < PW; ++j) {
        bool empty = hempty || (we[j] <= ws[j]);
        op[j] = empty ? 0.0f : acc[j];
    }
}

extern "C" void kernel_launch(void* const* d_in, const int* in_sizes, int n_in,
                              void* d_out, int out_size) {
    const float* feat = (const float*)d_in[0];
    const float* rois = (const float*)d_in[1];
    float* out = (float*)d_out;

    int K = in_sizes[1] / 5;   // 256

    dim3 tgrid((HW + 31) / 32, C_DIM / 32, N_IMG);   // 79 x 4 x 4
    dim3 tblk(32, 8);
    transpose_kernel<<<tgrid, tblk>>>(feat);

    dim3 pgrid(K, PH);
    roi_pool_kernel<<<pgrid, C_DIM>>>(rois, out);
}

// round 11
// speedup vs baseline: 1.7347x; 1.7347x over previous
#include <cuda_runtime.h>

#define PH 7
#define PW 7
#define ROI_SCALE 0.0625f

#define N_IMG 4
#define C_DIM 128
#define H_DIM 50
#define W_DIM 50
#define HW (H_DIM * W_DIM)

// Bit-exact vs the as-executed JAX reference: x/7 computed as x * fl(1/7),
// fl(1/7) = 0x3E124925 (rounds up). DO NOT change.
#define RECIP7_BITS 0x3E124925u

// NHWC scratch: [b][h][w][c]  (5.12 MB static device array — no allocation)
__device__ float g_featT[N_IMG * HW * C_DIM];

// ---------------- NCHW -> NHWC transpose ------------------------------------
__global__ void transpose_kernel(const float* __restrict__ feat) {
    __shared__ float tile[32][33];
    int b   = blockIdx.z;
    int hw0 = blockIdx.x * 32;
    int c0  = blockIdx.y * 32;

    const float* src = feat + (size_t)b * C_DIM * HW;
    float* dst = g_featT + (size_t)b * HW * C_DIM;

    int tx = threadIdx.x;   // 0..31
    int ty = threadIdx.y;   // 0..7

#pragma unroll
    for (int j = 0; j < 32; j += 8) {
        int c  = c0 + ty + j;
        int hw = hw0 + tx;
        if (hw < HW)
            tile[ty + j][tx] = src[c * HW + hw];
    }
    __syncthreads();
#pragma unroll
    for (int j = 0; j < 32; j += 8) {
        int hw = hw0 + ty + j;
        int c  = c0 + tx;
        if (hw < HW)
            dst[hw * C_DIM + c] = tile[tx][ty + j];
    }
}

// --------- pooling: block = one (k, ph, pw) bin; thread = channel -----------
__global__ void __launch_bounds__(C_DIM) roi_pool_kernel(
        const float* __restrict__ rois,
        float* __restrict__ out) {
    int k  = blockIdx.x;
    int ph = blockIdx.y;
    int pw = blockIdx.z;
    int c  = threadIdx.x;

    // Uniform per-block decode (warp-uniform branches below).
    const float* r = rois + k * 5;
    int b  = (int)r[0];
    int x1 = (int)rintf(__fmul_rn(r[1], ROI_SCALE));
    int y1 = (int)rintf(__fmul_rn(r[2], ROI_SCALE));
    int x2 = (int)rintf(__fmul_rn(r[3], ROI_SCALE));
    int y2 = (int)rintf(__fmul_rn(r[4], ROI_SCALE));

    float roi_w = (float)max(x2 - x1 + 1, 1);
    float roi_h = (float)max(y2 - y1 + 1, 1);
    const float recip7 = __uint_as_float(RECIP7_BITS);
    float bin_w = __fmul_rn(roi_w, recip7);
    float bin_h = __fmul_rn(roi_h, recip7);

    float phf = (float)ph;
    float pwf = (float)pw;
    int hstart = min(max((int)floorf(__fmul_rn(phf, bin_h)) + y1, 0), H_DIM);
    int hend   = min(max((int)ceilf(__fmul_rn(phf + 1.0f, bin_h)) + y1, 0), H_DIM);
    int wstart = min(max((int)floorf(__fmul_rn(pwf, bin_w)) + x1, 0), W_DIM);
    int wend   = min(max((int)ceilf(__fmul_rn(pwf + 1.0f, bin_w)) + x1, 0), W_DIM);

    const float* baseb = g_featT + (size_t)b * HW * C_DIM + c;

    float m = -1e30f;
    for (int h = hstart; h < hend; ++h) {
        const float* rowp = baseb + h * (W_DIM * C_DIM);
        for (int w = wstart; w < wend; ++w) {
            m = fmaxf(m, rowp[w * C_DIM]);    // 128B coalesced per warp
        }
    }

    bool empty = (hend <= hstart) || (wend <= wstart);
    out[(((size_t)k * C_DIM + c) * PH + ph) * PW + pw] = empty ? 0.0f : m;
}

extern "C" void kernel_launch(void* const* d_in, const int* in_sizes, int n_in,
                              void* d_out, int out_size) {
    const float* feat = (const float*)d_in[0];
    const float* rois = (const float*)d_in[1];
    float* out = (float*)d_out;

    int K = in_sizes[1] / 5;   // 256

    dim3 tgrid((HW + 31) / 32, C_DIM / 32, N_IMG);
    dim3 tblk(32, 8);
    transpose_kernel<<<tgrid, tblk>>>(feat);

    dim3 pgrid(K, PH, PW);     // 256 x 7 x 7 = 12544 blocks
    roi_pool_kernel<<<pgrid, C_DIM>>>(rois, out);
}